// round 1
// baseline (speedup 1.0000x reference)
#include <cuda_runtime.h>

#define N_NODES 50000
#define N_EDGES 200000
#define FEAT 64
#define MUL 16
#define ALPHA 0.17677669529663687f
#define INV_SQRT3 0.5773502691896258f
#define AIS (ALPHA * INV_SQRT3)
#define BN_EPS 1e-5f
#define SW 272  // w_s row stride (floats): 272%32==16 -> conflict-free phase-B reads

// ---------------- scratch (device globals; no allocation allowed) ----------------
__device__ float g_H[N_EDGES * 64];     // relu(edge_attr @ w1 + b1)
__device__ float g_agg[N_NODES * 64];   // segment sum accumulator
__device__ float g_cnt[N_NODES];        // segment counts
__device__ float g_out[N_NODES * 64];   // pre-BN output
__device__ float g_stats[48];           // sum_s[16], sumsq_s[16], sum_v2[16]
__device__ float g_norm[48];            // mean_s[16], scale_s[16], scale_v[16]

// ---------------- kernel 0: zero accumulators ----------------
__global__ void k_zero() {
    int idx = blockIdx.x * blockDim.x + threadIdx.x;
    int stride = gridDim.x * blockDim.x;
    for (int i = idx; i < N_NODES * 64; i += stride) g_agg[i] = 0.0f;
    for (int i = idx; i < N_NODES; i += stride) g_cnt[i] = 0.0f;
    if (idx < 48) g_stats[idx] = 0.0f;
}

// ---------------- kernel 1: H = relu(EA @ W1 + b1) ----------------
__global__ __launch_bounds__(256) void k_gemm1(const float* __restrict__ ea,
                                               const float* __restrict__ w1,
                                               const float* __restrict__ b1) {
    __shared__ float eaT[64][68];  // [j][e], padded
    __shared__ float w1s[64][64];  // [j][c]
    int tid = threadIdx.x;
    int e0 = blockIdx.x * 64;

    for (int idx = tid; idx < 64 * 64; idx += 256) {
        int e = idx >> 6, j = idx & 63;
        eaT[j][e] = ea[(e0 + e) * 64 + j];
        w1s[idx >> 6][idx & 63] = w1[idx];
    }
    __syncthreads();

    int te = (tid >> 4) << 2;
    int tc = (tid & 15) << 2;
    float acc[4][4];
#pragma unroll
    for (int a = 0; a < 4; a++)
#pragma unroll
        for (int b = 0; b < 4; b++) acc[a][b] = 0.0f;

#pragma unroll 4
    for (int j = 0; j < 64; j++) {
        float4 av = *(const float4*)&eaT[j][te];
        float4 wv = *(const float4*)&w1s[j][tc];
        float ar[4] = {av.x, av.y, av.z, av.w};
        float wr[4] = {wv.x, wv.y, wv.z, wv.w};
#pragma unroll
        for (int a = 0; a < 4; a++)
#pragma unroll
            for (int b = 0; b < 4; b++) acc[a][b] = fmaf(ar[a], wr[b], acc[a][b]);
    }
#pragma unroll
    for (int a = 0; a < 4; a++) {
        float4 o;
        o.x = fmaxf(acc[a][0] + b1[tc + 0], 0.0f);
        o.y = fmaxf(acc[a][1] + b1[tc + 1], 0.0f);
        o.z = fmaxf(acc[a][2] + b1[tc + 2], 0.0f);
        o.w = fmaxf(acc[a][3] + b1[tc + 3], 0.0f);
        *(float4*)&g_H[(e0 + te + a) * 64 + tc] = o;
    }
}

// ---------------- kernel 2: fused GEMM2 + tensor product + scatter ----------------
// Block: 256 threads, 64 edges. Loop over 4 chunks (t = ss/vv/sv/vs, 256 cols each):
//   phase A: w[64e][256c] = h @ W2chunk + b2 (8x8 register tiles), staged to smem
//   phase B: contract w with per-edge coefficients; (edge,k) ownership exclusive.
__global__ __launch_bounds__(256) void k_tp(const float* __restrict__ node_attr,
                                            const float* __restrict__ edge_sh,
                                            const float* __restrict__ w2,
                                            const float* __restrict__ b2,
                                            const int* __restrict__ edge_index) {
    extern __shared__ __align__(16) float sm[];
    float* hT  = sm;                   // [64][68]  (j-major, padded)
    float* w2s = hT + 64 * 68;         // [64][256] (j-major chunk of W2)
    float* w_s = w2s + 64 * 256;       // [64][SW]  (edge-major w values)
    float* cA  = w_s + 64 * SW;        // [64][16]  ALPHA*ss*xs
    float* cXS = cA + 1024;            // [64][16]  AIS*xs
    float* cB  = cXS + 1024;           // [64][16]  AIS*(xv . sv)
    float* cD  = cB + 1024;            // [64][48]  AIS*ss*xv
    float* xvr = cD + 3072;            // [64][48]  raw xv
    float* shs = xvr + 3072;           // [64][4]
    float* b2s = shs + 256;            // [256]
    __shared__ int srcs[64], dsts[64];

    int tid = threadIdx.x;
    int e0 = blockIdx.x * 64;

    if (tid < 64) {
        srcs[tid] = edge_index[e0 + tid];
        dsts[tid] = edge_index[N_EDGES + e0 + tid];
    }
    if (tid < 256) shs[tid] = edge_sh[e0 * 4 + tid];
    for (int idx = tid; idx < 4096; idx += 256) {
        int e = idx >> 6, j = idx & 63;
        hT[j * 68 + e] = g_H[(e0 + e) * 64 + j];
    }
    __syncthreads();

    // gather node features, build coefficients
    for (int idx = tid; idx < 4096; idx += 256) {
        int e = idx >> 6, f = idx & 63;
        float v = node_attr[dsts[e] * 64 + f];
        float ssv = shs[e * 4];
        if (f < 16) {
            cA[e * 16 + f] = ALPHA * ssv * v;
            cXS[e * 16 + f] = AIS * v;
        } else {
            int g = f - 16;
            cD[e * 48 + g] = AIS * ssv * v;
            xvr[e * 48 + g] = v;
        }
    }
    __syncthreads();
    for (int idx = tid; idx < 1024; idx += 256) {
        int e = idx >> 4, i = idx & 15;
        cB[idx] = AIS * (xvr[e * 48 + i * 3 + 0] * shs[e * 4 + 1] +
                         xvr[e * 48 + i * 3 + 1] * shs[e * 4 + 2] +
                         xvr[e * 48 + i * 3 + 2] * shs[e * 4 + 3]);
    }

    // persistent phase-B accumulators: thread owns k=tid&15 for edges eB+16s
    float s_acc[4] = {0, 0, 0, 0};
    float r_acc[4] = {0, 0, 0, 0};
    float v_acc[4][3] = {{0, 0, 0}, {0, 0, 0}, {0, 0, 0}, {0, 0, 0}};
    int eB = tid >> 4;
    int kB = tid & 15;

    for (int t = 0; t < 4; t++) {
        __syncthreads();  // protect w2s reload / w_s rewrite vs previous phase B
        for (int idx = tid; idx < 16384; idx += 256) {
            int j = idx >> 8, c = idx & 255;
            w2s[idx] = w2[j * 1024 + t * 256 + c];
        }
        b2s[tid] = b2[t * 256 + tid];
        __syncthreads();

        // --- phase A: 8x8 register-tile GEMM, 64e x 256c ---
        int eg = tid >> 5, cg = tid & 31;
        int ebase = eg * 8, c0 = cg * 8;
        float acc[8][8];
#pragma unroll
        for (int a = 0; a < 8; a++)
#pragma unroll
            for (int b = 0; b < 8; b++) acc[a][b] = 0.0f;

#pragma unroll 4
        for (int j = 0; j < 64; j++) {
            float4 h0 = *(const float4*)&hT[j * 68 + ebase];
            float4 h1 = *(const float4*)&hT[j * 68 + ebase + 4];
            float4 q0 = *(const float4*)&w2s[j * 256 + c0];
            float4 q1 = *(const float4*)&w2s[j * 256 + c0 + 4];
            float hv[8] = {h0.x, h0.y, h0.z, h0.w, h1.x, h1.y, h1.z, h1.w};
            float wv[8] = {q0.x, q0.y, q0.z, q0.w, q1.x, q1.y, q1.z, q1.w};
#pragma unroll
            for (int a = 0; a < 8; a++)
#pragma unroll
                for (int b = 0; b < 8; b++) acc[a][b] = fmaf(hv[a], wv[b], acc[a][b]);
        }
#pragma unroll
        for (int a = 0; a < 8; a++) {
#pragma unroll
            for (int b = 0; b < 8; b++) acc[a][b] += b2s[c0 + b];
            *(float4*)&w_s[(ebase + a) * SW + c0] =
                make_float4(acc[a][0], acc[a][1], acc[a][2], acc[a][3]);
            *(float4*)&w_s[(ebase + a) * SW + c0 + 4] =
                make_float4(acc[a][4], acc[a][5], acc[a][6], acc[a][7]);
        }
        __syncthreads();

        // --- phase B: contract chunk t into per-thread accumulators ---
#pragma unroll
        for (int s = 0; s < 4; s++) {
            int e = eB + s * 16;
            const float* wrow = &w_s[e * SW + kB];
            if (t == 0) {
                float a = 0.0f;
#pragma unroll
                for (int i = 0; i < 16; i++) a = fmaf(cA[e * 16 + i], wrow[i * 16], a);
                s_acc[s] += a;
            } else if (t == 1) {
                float a = 0.0f;
#pragma unroll
                for (int i = 0; i < 16; i++) a = fmaf(cB[e * 16 + i], wrow[i * 16], a);
                s_acc[s] += a;
            } else if (t == 2) {
                float a = 0.0f;
#pragma unroll
                for (int i = 0; i < 16; i++) a = fmaf(cXS[e * 16 + i], wrow[i * 16], a);
                r_acc[s] += a;
            } else {
                float a0 = 0.0f, a1 = 0.0f, a2 = 0.0f;
#pragma unroll
                for (int i = 0; i < 16; i++) {
                    float wv = wrow[i * 16];
                    a0 = fmaf(cD[e * 48 + i * 3 + 0], wv, a0);
                    a1 = fmaf(cD[e * 48 + i * 3 + 1], wv, a1);
                    a2 = fmaf(cD[e * 48 + i * 3 + 2], wv, a2);
                }
                v_acc[s][0] += a0;
                v_acc[s][1] += a1;
                v_acc[s][2] += a2;
            }
        }
    }

    // --- scatter: agg[src] += tp ---
#pragma unroll
    for (int s = 0; s < 4; s++) {
        int e = eB + s * 16;
        int src = srcs[e];
        float sv0 = shs[e * 4 + 1], sv1 = shs[e * 4 + 2], sv2 = shs[e * 4 + 3];
        atomicAdd(&g_agg[src * 64 + kB], s_acc[s]);
        atomicAdd(&g_agg[src * 64 + 16 + kB * 3 + 0], v_acc[s][0] + sv0 * r_acc[s]);
        atomicAdd(&g_agg[src * 64 + 16 + kB * 3 + 1], v_acc[s][1] + sv1 * r_acc[s]);
        atomicAdd(&g_agg[src * 64 + 16 + kB * 3 + 2], v_acc[s][2] + sv2 * r_acc[s]);
        if (kB == 0) atomicAdd(&g_cnt[src], 1.0f);
    }
}

// ---------------- kernel 3: mean + residual + BN stats ----------------
__global__ __launch_bounds__(256) void k_stats(const float* __restrict__ node_attr) {
    int n = blockIdx.x * 256 + threadIdx.x;
    float ss[16], sq[16], v2[16];
#pragma unroll
    for (int c = 0; c < 16; c++) { ss[c] = 0.0f; sq[c] = 0.0f; v2[c] = 0.0f; }

    if (n < N_NODES) {
        float inv = 1.0f / fmaxf(g_cnt[n], 1.0f);
#pragma unroll
        for (int c = 0; c < 16; c++) {
            float o = g_agg[n * 64 + c] * inv + node_attr[n * 64 + c];
            g_out[n * 64 + c] = o;
            ss[c] = o;
            sq[c] = o * o;
        }
#pragma unroll
        for (int c = 0; c < 16; c++) {
            int f = 16 + 3 * c;
            float a = g_agg[n * 64 + f + 0] * inv + node_attr[n * 64 + f + 0];
            float b = g_agg[n * 64 + f + 1] * inv + node_attr[n * 64 + f + 1];
            float d = g_agg[n * 64 + f + 2] * inv + node_attr[n * 64 + f + 2];
            g_out[n * 64 + f + 0] = a;
            g_out[n * 64 + f + 1] = b;
            g_out[n * 64 + f + 2] = d;
            v2[c] = a * a + b * b + d * d;
        }
    }
#pragma unroll
    for (int c = 0; c < 16; c++) {
#pragma unroll
        for (int o = 16; o > 0; o >>= 1) {
            ss[c] += __shfl_down_sync(0xffffffffu, ss[c], o);
            sq[c] += __shfl_down_sync(0xffffffffu, sq[c], o);
            v2[c] += __shfl_down_sync(0xffffffffu, v2[c], o);
        }
    }
    if ((threadIdx.x & 31) == 0) {
#pragma unroll
        for (int c = 0; c < 16; c++) {
            atomicAdd(&g_stats[c], ss[c]);
            atomicAdd(&g_stats[16 + c], sq[c]);
            atomicAdd(&g_stats[32 + c], v2[c]);
        }
    }
}

// ---------------- kernel 4: finalize BN params ----------------
__global__ void k_finalize(const float* __restrict__ bn_weight) {
    int t = threadIdx.x;
    if (t < 16) {
        float mean = g_stats[t] * (1.0f / N_NODES);
        float var = g_stats[16 + t] * (1.0f / N_NODES) - mean * mean;
        g_norm[t] = mean;
        g_norm[16 + t] = bn_weight[t] * rsqrtf(var + BN_EPS);
        float fn = g_stats[32 + t] * (1.0f / (3.0f * N_NODES));
        g_norm[32 + t] = bn_weight[16 + t] * rsqrtf(fn + BN_EPS);
    }
}

// ---------------- kernel 5: normalize ----------------
__global__ void k_norm(const float* __restrict__ bn_bias, float* __restrict__ out) {
    int idx = blockIdx.x * blockDim.x + threadIdx.x;
    if (idx >= N_NODES * 64) return;
    int f = idx & 63;
    float o = g_out[idx];
    if (f < 16)
        out[idx] = (o - g_norm[f]) * g_norm[16 + f] + bn_bias[f];
    else
        out[idx] = o * g_norm[32 + (f - 16) / 3];
}

// ---------------- launch ----------------
extern "C" void kernel_launch(void* const* d_in, const int* in_sizes, int n_in,
                              void* d_out, int out_size) {
    const float* node_attr = (const float*)d_in[0];
    const float* edge_attr = (const float*)d_in[1];
    const float* edge_sh = (const float*)d_in[2];
    const float* w1 = (const float*)d_in[3];
    const float* b1 = (const float*)d_in[4];
    const float* w2 = (const float*)d_in[5];
    const float* b2 = (const float*)d_in[6];
    const float* bnw = (const float*)d_in[7];
    const float* bnb = (const float*)d_in[8];
    const int* eidx = (const int*)d_in[9];
    float* out = (float*)d_out;

    const int SMEM_TP = (64 * 68 + 64 * 256 + 64 * SW + 3 * 1024 + 2 * 3072 + 256 + 256) * 4;
    cudaFuncSetAttribute(k_tp, cudaFuncAttributeMaxDynamicSharedMemorySize, SMEM_TP);

    k_zero<<<512, 256>>>();
    k_gemm1<<<N_EDGES / 64, 256>>>(edge_attr, w1, b1);
    k_tp<<<N_EDGES / 64, 256, SMEM_TP>>>(node_attr, edge_sh, w2, b2, eidx);
    k_stats<<<(N_NODES + 255) / 256, 256>>>(node_attr);
    k_finalize<<<1, 32>>>(bnw);
    k_norm<<<(N_NODES * 64 + 255) / 256, 256>>>(bnb, out);
}

// round 2
// speedup vs baseline: 1.0192x; 1.0192x over previous
#include <cuda_runtime.h>

#define N_NODES 50000
#define N_EDGES 200000
#define MUL 16
#define ALPHA 0.17677669529663687f
#define INV_SQRT3 0.5773502691896258f
#define AIS (ALPHA * INV_SQRT3)
#define BN_EPS 1e-5f
#define SW 272   // w_s row stride (floats): 272%32==16 -> conflict-free phase-B reads
#define HS 132   // hT2 row stride (floats): 16B-aligned rows for ulonglong2 loads

typedef unsigned long long ull;

// packed fp32x2 helpers (sm_100+: SASS FFMA2 / dual-rate fp32)
__device__ __forceinline__ ull ffma2(ull a, ull b, ull c) {
    ull d;
    asm("fma.rn.f32x2 %0, %1, %2, %3;" : "=l"(d) : "l"(a), "l"(b), "l"(c));
    return d;
}
__device__ __forceinline__ ull fadd2(ull a, ull b) {
    ull d;
    asm("add.rn.f32x2 %0, %1, %2;" : "=l"(d) : "l"(a), "l"(b));
    return d;
}
__device__ __forceinline__ void unpack2(float& lo, float& hi, ull v) {
    asm("mov.b64 {%0, %1}, %2;" : "=f"(lo), "=f"(hi) : "l"(v));
}

// ---------------- scratch (device globals; no allocation allowed) ----------------
__device__ float g_H[N_EDGES * 64];     // relu(edge_attr @ w1 + b1)
__device__ float g_agg[N_NODES * 64];   // segment sum accumulator
__device__ float g_cnt[N_NODES];        // segment counts
__device__ float g_out[N_NODES * 64];   // pre-BN output
__device__ float g_stats[48];           // sum_s[16], sumsq_s[16], sum_v2[16]
__device__ float g_norm[48];            // mean_s[16], scale_s[16], scale_v[16]

// ---------------- kernel 0: zero accumulators ----------------
__global__ void k_zero() {
    int idx = blockIdx.x * blockDim.x + threadIdx.x;
    int stride = gridDim.x * blockDim.x;
    for (int i = idx; i < N_NODES * 64; i += stride) g_agg[i] = 0.0f;
    for (int i = idx; i < N_NODES; i += stride) g_cnt[i] = 0.0f;
    if (idx < 48) g_stats[idx] = 0.0f;
}

// ---------------- kernel 1: H = relu(EA @ W1 + b1), f32x2 ----------------
__global__ __launch_bounds__(256) void k_gemm1(const float* __restrict__ ea,
                                               const float* __restrict__ w1,
                                               const float* __restrict__ b1) {
    extern __shared__ __align__(16) float smg[];
    float* eaT2 = smg;            // [64][HS]  ea transposed, value-duplicated pairs
    float* w1s = eaT2 + 64 * HS;  // [64][64]
    int tid = threadIdx.x;
    int e0 = blockIdx.x * 64;

    for (int idx = tid; idx < 4096; idx += 256) {
        int e = idx >> 6, j = idx & 63;
        float v = ea[(e0 + e) * 64 + j];
        eaT2[j * HS + 2 * e] = v;
        eaT2[j * HS + 2 * e + 1] = v;
        w1s[idx] = w1[idx];
    }
    __syncthreads();

    int te = (tid >> 4) << 2;
    int tc = (tid & 15) << 2;
    ull acc2[4][2];
#pragma unroll
    for (int a = 0; a < 4; a++) { acc2[a][0] = 0ULL; acc2[a][1] = 0ULL; }

#pragma unroll 4
    for (int j = 0; j < 64; j++) {
        ulonglong2 e01 = *(const ulonglong2*)&eaT2[j * HS + 2 * te];
        ulonglong2 e23 = *(const ulonglong2*)&eaT2[j * HS + 2 * te + 4];
        ulonglong2 wq = *(const ulonglong2*)&w1s[j * 64 + tc];
        ull hd[4] = {e01.x, e01.y, e23.x, e23.y};
        ull wp[2] = {wq.x, wq.y};
#pragma unroll
        for (int a = 0; a < 4; a++)
#pragma unroll
            for (int p = 0; p < 2; p++) acc2[a][p] = ffma2(hd[a], wp[p], acc2[a][p]);
    }

    float bb[4] = {b1[tc], b1[tc + 1], b1[tc + 2], b1[tc + 3]};
#pragma unroll
    for (int a = 0; a < 4; a++) {
        float o0, o1, o2, o3;
        unpack2(o0, o1, acc2[a][0]);
        unpack2(o2, o3, acc2[a][1]);
        float4 o;
        o.x = fmaxf(o0 + bb[0], 0.0f);
        o.y = fmaxf(o1 + bb[1], 0.0f);
        o.z = fmaxf(o2 + bb[2], 0.0f);
        o.w = fmaxf(o3 + bb[3], 0.0f);
        *(float4*)&g_H[(e0 + te + a) * 64 + tc] = o;
    }
}

// ---------------- kernel 2: fused GEMM2 (f32x2) + tensor product + scatter ----------------
__global__ __launch_bounds__(256) void k_tp(const float* __restrict__ node_attr,
                                            const float* __restrict__ edge_sh,
                                            const float* __restrict__ w2,
                                            const float* __restrict__ b2,
                                            const int* __restrict__ edge_index) {
    extern __shared__ __align__(16) float sm[];
    float* hT2 = sm;                   // [64][HS]  h transposed, value-duplicated pairs
    float* w2s = hT2 + 64 * HS;        // [64][256] j-major chunk of W2
    float* w_s = w2s + 64 * 256;       // [64][SW]  edge-major w values
    float* cA  = w_s + 64 * SW;        // [64][16]  ALPHA*ss*xs
    float* cXS = cA + 1024;            // [64][16]  AIS*xs
    float* cB  = cXS + 1024;           // [64][16]  AIS*(xv . sv)
    float* cD  = cB + 1024;            // [64][48]  AIS*ss*xv
    float* shs = cD + 3072;            // [64][4]
    float* b2s = shs + 256;            // [256]
    __shared__ int srcs[64], dsts[64];

    int tid = threadIdx.x;
    int e0 = blockIdx.x * 64;

    if (tid < 64) {
        srcs[tid] = edge_index[e0 + tid];
        dsts[tid] = edge_index[N_EDGES + e0 + tid];
    }
    if (tid < 256) shs[tid] = edge_sh[e0 * 4 + tid];
    for (int idx = tid; idx < 4096; idx += 256) {
        int e = idx >> 6, j = idx & 63;
        float v = g_H[(e0 + e) * 64 + j];
        hT2[j * HS + 2 * e] = v;
        hT2[j * HS + 2 * e + 1] = v;
    }
    __syncthreads();

    // per-edge coefficients
    for (int idx = tid; idx < 1024; idx += 256) {
        int e = idx >> 4, i = idx & 15;
        float xs = node_attr[dsts[e] * 64 + i];
        float ssv = shs[e * 4];
        cA[idx] = ALPHA * ssv * xs;
        cXS[idx] = AIS * xs;
    }
    for (int idx = tid; idx < 1024; idx += 256) {
        int e = idx >> 4, i = idx & 15;
        const float* xp = &node_attr[dsts[e] * 64 + 16 + 3 * i];
        float x0 = xp[0], x1 = xp[1], x2 = xp[2];
        float ssv = shs[e * 4];
        float s1 = shs[e * 4 + 1], s2 = shs[e * 4 + 2], s3 = shs[e * 4 + 3];
        cD[e * 48 + 3 * i + 0] = AIS * ssv * x0;
        cD[e * 48 + 3 * i + 1] = AIS * ssv * x1;
        cD[e * 48 + 3 * i + 2] = AIS * ssv * x2;
        cB[idx] = AIS * (x0 * s1 + x1 * s2 + x2 * s3);
    }

    // persistent phase-B accumulators: thread owns k=tid&15 for edges eB+16s
    float s_acc[4] = {0, 0, 0, 0};
    float r_acc[4] = {0, 0, 0, 0};
    float v_acc[4][3] = {{0, 0, 0}, {0, 0, 0}, {0, 0, 0}, {0, 0, 0}};
    int eB = tid >> 4;
    int kB = tid & 15;

    for (int t = 0; t < 4; t++) {
        __syncthreads();  // protect w2s reload / w_s rewrite vs previous phase B
        for (int idx = tid; idx < 16384; idx += 256) {
            int j = idx >> 8, c = idx & 255;
            w2s[idx] = w2[j * 1024 + t * 256 + c];
        }
        b2s[tid] = b2[t * 256 + tid];
        __syncthreads();

        // --- phase A: 8x8 tile GEMM via FFMA2, 64e x 256c ---
        int eg = tid >> 5, lane = tid & 31;
        int ebase = eg * 8, c0 = lane * 8;
        ull acc2[8][4];
#pragma unroll
        for (int a = 0; a < 8; a++)
#pragma unroll
            for (int p = 0; p < 4; p++) acc2[a][p] = 0ULL;

#pragma unroll 2
        for (int j = 0; j < 64; j++) {
            const float* hrow = &hT2[j * HS + eg * 16];
            ulonglong2 h01 = *(const ulonglong2*)(hrow);
            ulonglong2 h23 = *(const ulonglong2*)(hrow + 4);
            ulonglong2 h45 = *(const ulonglong2*)(hrow + 8);
            ulonglong2 h67 = *(const ulonglong2*)(hrow + 12);
            const float* wrow = &w2s[j * 256 + c0];
            ulonglong2 w01 = *(const ulonglong2*)(wrow);
            ulonglong2 w23 = *(const ulonglong2*)(wrow + 4);
            ull hd[8] = {h01.x, h01.y, h23.x, h23.y, h45.x, h45.y, h67.x, h67.y};
            ull wp[4] = {w01.x, w01.y, w23.x, w23.y};
#pragma unroll
            for (int a = 0; a < 8; a++)
#pragma unroll
                for (int p = 0; p < 4; p++) acc2[a][p] = ffma2(hd[a], wp[p], acc2[a][p]);
        }

        ull bp[4];
        bp[0] = *(const ull*)&b2s[c0];
        bp[1] = *(const ull*)&b2s[c0 + 2];
        bp[2] = *(const ull*)&b2s[c0 + 4];
        bp[3] = *(const ull*)&b2s[c0 + 6];
#pragma unroll
        for (int a = 0; a < 8; a++) {
            ulonglong2 s0, s1;
            s0.x = fadd2(acc2[a][0], bp[0]);
            s0.y = fadd2(acc2[a][1], bp[1]);
            s1.x = fadd2(acc2[a][2], bp[2]);
            s1.y = fadd2(acc2[a][3], bp[3]);
            *(ulonglong2*)&w_s[(ebase + a) * SW + c0] = s0;
            *(ulonglong2*)&w_s[(ebase + a) * SW + c0 + 4] = s1;
        }
        __syncthreads();

        // --- phase B: contract chunk t into per-thread accumulators ---
#pragma unroll
        for (int s = 0; s < 4; s++) {
            int e = eB + s * 16;
            const float* wrow = &w_s[e * SW + kB];
            if (t == 0) {
                float a = 0.0f;
#pragma unroll
                for (int i = 0; i < 16; i++) a = fmaf(cA[e * 16 + i], wrow[i * 16], a);
                s_acc[s] += a;
            } else if (t == 1) {
                float a = 0.0f;
#pragma unroll
                for (int i = 0; i < 16; i++) a = fmaf(cB[e * 16 + i], wrow[i * 16], a);
                s_acc[s] += a;
            } else if (t == 2) {
                float a = 0.0f;
#pragma unroll
                for (int i = 0; i < 16; i++) a = fmaf(cXS[e * 16 + i], wrow[i * 16], a);
                r_acc[s] += a;
            } else {
                float a0 = 0.0f, a1 = 0.0f, a2 = 0.0f;
#pragma unroll
                for (int i = 0; i < 16; i++) {
                    float wv = wrow[i * 16];
                    a0 = fmaf(cD[e * 48 + i * 3 + 0], wv, a0);
                    a1 = fmaf(cD[e * 48 + i * 3 + 1], wv, a1);
                    a2 = fmaf(cD[e * 48 + i * 3 + 2], wv, a2);
                }
                v_acc[s][0] += a0;
                v_acc[s][1] += a1;
                v_acc[s][2] += a2;
            }
        }
    }

    // --- scatter: agg[src] += tp ---
#pragma unroll
    for (int s = 0; s < 4; s++) {
        int e = eB + s * 16;
        int src = srcs[e];
        float sv0 = shs[e * 4 + 1], sv1 = shs[e * 4 + 2], sv2 = shs[e * 4 + 3];
        atomicAdd(&g_agg[src * 64 + kB], s_acc[s]);
        atomicAdd(&g_agg[src * 64 + 16 + kB * 3 + 0], v_acc[s][0] + sv0 * r_acc[s]);
        atomicAdd(&g_agg[src * 64 + 16 + kB * 3 + 1], v_acc[s][1] + sv1 * r_acc[s]);
        atomicAdd(&g_agg[src * 64 + 16 + kB * 3 + 2], v_acc[s][2] + sv2 * r_acc[s]);
        if (kB == 0) atomicAdd(&g_cnt[src], 1.0f);
    }
}

// ---------------- kernel 3: mean + residual + BN stats (coalesced) ----------------
__global__ __launch_bounds__(256) void k_stats(const float* __restrict__ node_attr) {
    __shared__ float sstat[48];
    int tid = threadIdx.x;
    if (tid < 48) sstat[tid] = 0.0f;
    __syncthreads();

    int n = blockIdx.x * 16 + (tid >> 4);
    int q = tid & 15;
    if (n < N_NODES) {
        float inv = 1.0f / fmaxf(g_cnt[n], 1.0f);
        float4 ag = *(const float4*)&g_agg[n * 64 + q * 4];
        float4 na = *(const float4*)&node_attr[n * 64 + q * 4];
        float o[4] = {fmaf(ag.x, inv, na.x), fmaf(ag.y, inv, na.y),
                      fmaf(ag.z, inv, na.z), fmaf(ag.w, inv, na.w)};
        *(float4*)&g_out[n * 64 + q * 4] = make_float4(o[0], o[1], o[2], o[3]);
        if (q < 4) {
#pragma unroll
            for (int t = 0; t < 4; t++) {
                atomicAdd(&sstat[q * 4 + t], o[t]);
                atomicAdd(&sstat[16 + q * 4 + t], o[t] * o[t]);
            }
        } else {
#pragma unroll
            for (int t = 0; t < 4; t++) {
                int k = (q * 4 + t - 16) / 3;
                atomicAdd(&sstat[32 + k], o[t] * o[t]);
            }
        }
    }
    __syncthreads();
    if (tid < 48) atomicAdd(&g_stats[tid], sstat[tid]);
}

// ---------------- kernel 4: finalize BN params ----------------
__global__ void k_finalize(const float* __restrict__ bn_weight) {
    int t = threadIdx.x;
    if (t < 16) {
        float mean = g_stats[t] * (1.0f / N_NODES);
        float var = g_stats[16 + t] * (1.0f / N_NODES) - mean * mean;
        g_norm[t] = mean;
        g_norm[16 + t] = bn_weight[t] * rsqrtf(var + BN_EPS);
        float fn = g_stats[32 + t] * (1.0f / (3.0f * N_NODES));
        g_norm[32 + t] = bn_weight[16 + t] * rsqrtf(fn + BN_EPS);
    }
}

// ---------------- kernel 5: normalize ----------------
__global__ void k_norm(const float* __restrict__ bn_bias, float* __restrict__ out) {
    int idx = blockIdx.x * blockDim.x + threadIdx.x;
    if (idx >= N_NODES * 64) return;
    int f = idx & 63;
    float o = g_out[idx];
    if (f < 16)
        out[idx] = (o - g_norm[f]) * g_norm[16 + f] + bn_bias[f];
    else
        out[idx] = o * g_norm[32 + (f - 16) / 3];
}

// ---------------- launch ----------------
extern "C" void kernel_launch(void* const* d_in, const int* in_sizes, int n_in,
                              void* d_out, int out_size) {
    const float* node_attr = (const float*)d_in[0];
    const float* edge_attr = (const float*)d_in[1];
    const float* edge_sh = (const float*)d_in[2];
    const float* w1 = (const float*)d_in[3];
    const float* b1 = (const float*)d_in[4];
    const float* w2 = (const float*)d_in[5];
    const float* b2 = (const float*)d_in[6];
    const float* bnw = (const float*)d_in[7];
    const float* bnb = (const float*)d_in[8];
    const int* eidx = (const int*)d_in[9];
    float* out = (float*)d_out;

    const int SMEM_G1 = (64 * HS + 64 * 64) * 4;
    const int SMEM_TP = (64 * HS + 64 * 256 + 64 * SW + 3 * 1024 + 3072 + 256 + 256) * 4;
    cudaFuncSetAttribute(k_gemm1, cudaFuncAttributeMaxDynamicSharedMemorySize, SMEM_G1);
    cudaFuncSetAttribute(k_tp, cudaFuncAttributeMaxDynamicSharedMemorySize, SMEM_TP);

    k_zero<<<512, 256>>>();
    k_gemm1<<<N_EDGES / 64, 256, SMEM_G1>>>(edge_attr, w1, b1);
    k_tp<<<N_EDGES / 64, 256, SMEM_TP>>>(node_attr, edge_sh, w2, b2, eidx);
    k_stats<<<(N_NODES + 15) / 16, 256>>>(node_attr);
    k_finalize<<<1, 32>>>(bnw);
    k_norm<<<(N_NODES * 64 + 255) / 256, 256>>>(bnb, out);
}

// round 3
// speedup vs baseline: 1.5509x; 1.5217x over previous
#include <cuda_runtime.h>

#define N_NODES 50000
#define N_EDGES 200000
#define MUL 16
#define ALPHA 0.17677669529663687f
#define INV_SQRT3 0.5773502691896258f
#define AIS (ALPHA * INV_SQRT3)
#define BN_EPS 1e-5f
#define HS 132   // k_gemm1 eaT2 row stride

typedef unsigned long long ull;

// packed fp32x2 helpers (sm_100+: dual-rate fp32)
__device__ __forceinline__ ull ffma2(ull a, ull b, ull c) {
    ull d;
    asm("fma.rn.f32x2 %0, %1, %2, %3;" : "=l"(d) : "l"(a), "l"(b), "l"(c));
    return d;
}
__device__ __forceinline__ ull fmul2(ull a, ull b) {
    ull d;
    asm("mul.rn.f32x2 %0, %1, %2;" : "=l"(d) : "l"(a), "l"(b));
    return d;
}
__device__ __forceinline__ ull fadd2(ull a, ull b) {
    ull d;
    asm("add.rn.f32x2 %0, %1, %2;" : "=l"(d) : "l"(a), "l"(b));
    return d;
}
__device__ __forceinline__ ull pack2(float lo, float hi) {
    ull d;
    asm("mov.b64 %0, {%1, %2};" : "=l"(d) : "f"(lo), "f"(hi));
    return d;
}
__device__ __forceinline__ void unpack2(float& lo, float& hi, ull v) {
    asm("mov.b64 {%0, %1}, %2;" : "=f"(lo), "=f"(hi) : "l"(v));
}
__device__ __forceinline__ ull shflx64(ull v, int m) {
    return __shfl_xor_sync(0xffffffffu, v, m);
}

// ---------------- scratch ----------------
__device__ float g_H[N_EDGES * 64];
__device__ float g_agg[N_NODES * 64];
__device__ float g_cnt[N_NODES];
__device__ float g_out[N_NODES * 64];
__device__ float g_stats[48];
__device__ float g_norm[48];

// ---------------- kernel 0: zero accumulators ----------------
__global__ void k_zero() {
    int idx = blockIdx.x * blockDim.x + threadIdx.x;
    int stride = gridDim.x * blockDim.x;
    for (int i = idx; i < N_NODES * 64; i += stride) g_agg[i] = 0.0f;
    for (int i = idx; i < N_NODES; i += stride) g_cnt[i] = 0.0f;
    if (idx < 48) g_stats[idx] = 0.0f;
}

// ---------------- kernel 1: H = relu(EA @ W1 + b1), f32x2 ----------------
__global__ __launch_bounds__(256) void k_gemm1(const float* __restrict__ ea,
                                               const float* __restrict__ w1,
                                               const float* __restrict__ b1) {
    extern __shared__ __align__(16) float smg[];
    float* eaT2 = smg;            // [64][HS] duplicated pairs
    float* w1s = eaT2 + 64 * HS;  // [64][64]
    int tid = threadIdx.x;
    int e0 = blockIdx.x * 64;

    for (int idx = tid; idx < 4096; idx += 256) {
        int e = idx >> 6, j = idx & 63;
        float v = ea[(e0 + e) * 64 + j];
        eaT2[j * HS + 2 * e] = v;
        eaT2[j * HS + 2 * e + 1] = v;
        w1s[idx] = w1[idx];
    }
    __syncthreads();

    int te = (tid >> 4) << 2;
    int tc = (tid & 15) << 2;
    ull acc2[4][2];
#pragma unroll
    for (int a = 0; a < 4; a++) { acc2[a][0] = 0ULL; acc2[a][1] = 0ULL; }

#pragma unroll 4
    for (int j = 0; j < 64; j++) {
        ulonglong2 e01 = *(const ulonglong2*)&eaT2[j * HS + 2 * te];
        ulonglong2 e23 = *(const ulonglong2*)&eaT2[j * HS + 2 * te + 4];
        ulonglong2 wq = *(const ulonglong2*)&w1s[j * 64 + tc];
        ull hd[4] = {e01.x, e01.y, e23.x, e23.y};
        ull wp[2] = {wq.x, wq.y};
#pragma unroll
        for (int a = 0; a < 4; a++)
#pragma unroll
            for (int p = 0; p < 2; p++) acc2[a][p] = ffma2(hd[a], wp[p], acc2[a][p]);
    }

    float bb[4] = {b1[tc], b1[tc + 1], b1[tc + 2], b1[tc + 3]};
#pragma unroll
    for (int a = 0; a < 4; a++) {
        float o0, o1, o2, o3;
        unpack2(o0, o1, acc2[a][0]);
        unpack2(o2, o3, acc2[a][1]);
        float4 o;
        o.x = fmaxf(o0 + bb[0], 0.0f);
        o.y = fmaxf(o1 + bb[1], 0.0f);
        o.z = fmaxf(o2 + bb[2], 0.0f);
        o.w = fmaxf(o3 + bb[3], 0.0f);
        *(float4*)&g_H[(e0 + te + a) * 64 + tc] = o;
    }
}

// ---------------- kernel 2: fused GEMM2 + TP via warp shuffles ----------------
// 256 threads, 64 edges/block, 2 blocks/SM. Warp w owns edges ebase=w*8..+7.
// 8 passes (t=0..3 x half=0..1), each 128 cols. Lane l covers cols c=l*4+q,
// so i = half*8 + (l>>2), k = (l&3)*4 + q; sum over i == shfl_xor {4,8,16}.
__global__ __launch_bounds__(256, 2) void k_tp(const float* __restrict__ node_attr,
                                               const float* __restrict__ edge_sh,
                                               const float* __restrict__ w2,
                                               const float* __restrict__ b2,
                                               const int* __restrict__ edge_index) {
    extern __shared__ __align__(16) float sm[];
    float* hT  = sm;               // [64][72]
    float* w2s = hT + 64 * 72;     // [64][128]
    float* cAT = w2s + 64 * 128;   // [16][66]  ALPHA*ss*xs      (i-major, e pairs)
    float* cBT = cAT + 1056;       // [16][66]  AIS*(xv.sv)
    float* cXT = cBT + 1056;       // [16][66]  AIS*xs
    float* cDT = cXT + 1056;       // [3][16][66] AIS*ss*xv_m
    float* sout = cDT + 3168;      // [64][16]
    float* rout = sout + 1024;     // [64][16]
    float* vout = rout + 1024;     // [64][48]
    float* b2s = vout + 3072;      // [1024]
    float* shsm = b2s + 1024;      // [64][4]
    __shared__ int srcs[64], dsts[64];

    int tid = threadIdx.x;
    int lane = tid & 31;
    int warp = tid >> 5;
    int ebase = warp * 8;
    int e0 = blockIdx.x * 64;

    if (tid < 64) {
        srcs[tid] = edge_index[e0 + tid];
        dsts[tid] = edge_index[N_EDGES + e0 + tid];
    }
    shsm[tid] = edge_sh[e0 * 4 + tid];
    for (int idx = tid; idx < 1024; idx += 256) b2s[idx] = b2[idx];
    for (int idx = tid; idx < 4096; idx += 256) {
        int e = idx >> 6, j = idx & 63;
        hT[j * 72 + e] = g_H[(e0 + e) * 64 + j];
    }
    for (int idx = tid; idx < 64 * 80; idx += 256) {
        if (idx < 1024) sout[idx] = 0.0f;
        else if (idx < 2048) rout[idx - 1024] = 0.0f;
        else vout[idx - 2048] = 0.0f;
    }
    __syncthreads();

    // per-edge coefficients (i-major transposed layouts, stride 66)
    for (int idx = tid; idx < 1024; idx += 256) {
        int e = idx >> 4, i = idx & 15;
        float xs = node_attr[dsts[e] * 64 + i];
        float ssv = shsm[e * 4];
        cAT[i * 66 + e] = ALPHA * ssv * xs;
        cXT[i * 66 + e] = AIS * xs;
    }
    for (int idx = tid; idx < 1024; idx += 256) {
        int e = idx >> 4, i = idx & 15;
        const float* xp = &node_attr[dsts[e] * 64 + 16 + 3 * i];
        float x0 = xp[0], x1 = xp[1], x2 = xp[2];
        float ssv = shsm[e * 4];
        float s1 = shsm[e * 4 + 1], s2 = shsm[e * 4 + 2], s3 = shsm[e * 4 + 3];
        cDT[0 * 1056 + i * 66 + e] = AIS * ssv * x0;
        cDT[1 * 1056 + i * 66 + e] = AIS * ssv * x1;
        cDT[2 * 1056 + i * 66 + e] = AIS * ssv * x2;
        cBT[i * 66 + e] = AIS * (x0 * s1 + x1 * s2 + x2 * s3);
    }

    int iL = lane >> 2;
    int kq = (lane & 3) * 4;

    for (int t = 0; t < 4; t++) {
        for (int half = 0; half < 2; half++) {
            __syncthreads();
            // load w2 half-chunk [64 j][128 c]
            for (int i = tid; i < 2048; i += 256) {
                int j = i >> 5, c4 = (i & 31) * 4;
                *(float4*)&w2s[j * 128 + c4] =
                    *(const float4*)&w2[j * 1024 + t * 256 + half * 128 + c4];
            }
            __syncthreads();

            // --- phase A: warp GEMM, 8 edges x 128 cols, FFMA2 pairs over edges ---
            ull acc[4][4];
#pragma unroll
            for (int p = 0; p < 4; p++)
#pragma unroll
                for (int c = 0; c < 4; c++) acc[p][c] = 0ULL;

#pragma unroll 2
            for (int j = 0; j < 64; j++) {
                const ull* hp = (const ull*)&hT[j * 72 + ebase];
                ull h0 = hp[0], h1 = hp[1], h2 = hp[2], h3 = hp[3];
                float4 wv = *(const float4*)&w2s[j * 128 + lane * 4];
                ull w0 = pack2(wv.x, wv.x);
                ull w1d = pack2(wv.y, wv.y);
                ull w2d = pack2(wv.z, wv.z);
                ull w3d = pack2(wv.w, wv.w);
                ull hd[4] = {h0, h1, h2, h3};
                ull wd[4] = {w0, w1d, w2d, w3d};
#pragma unroll
                for (int p = 0; p < 4; p++)
#pragma unroll
                    for (int c = 0; c < 4; c++) acc[p][c] = ffma2(hd[p], wd[c], acc[p][c]);
            }
            // bias
            const float* bptr = &b2s[t * 256 + half * 128 + lane * 4];
#pragma unroll
            for (int c = 0; c < 4; c++) {
                ull bd = pack2(bptr[c], bptr[c]);
#pragma unroll
                for (int p = 0; p < 4; p++) acc[p][c] = fadd2(acc[p][c], bd);
            }

            // --- phase B: coeff multiply + butterfly reduce over i ---
            int ig = half * 8 + iL;
            if (t < 3) {
                const float* C = (t == 0) ? cAT : (t == 1) ? cBT : cXT;
                ull cp[4];
#pragma unroll
                for (int p = 0; p < 4; p++) cp[p] = *(const ull*)&C[ig * 66 + ebase + 2 * p];
                ull tmp[4][4];
#pragma unroll
                for (int p = 0; p < 4; p++)
#pragma unroll
                    for (int c = 0; c < 4; c++) tmp[p][c] = fmul2(cp[p], acc[p][c]);
#pragma unroll
                for (int m = 4; m <= 16; m <<= 1)
#pragma unroll
                    for (int p = 0; p < 4; p++)
#pragma unroll
                        for (int c = 0; c < 4; c++)
                            tmp[p][c] = fadd2(tmp[p][c], shflx64(tmp[p][c], m));
                if (lane < 4) {
                    float* dst = (t == 2) ? rout : sout;
#pragma unroll
                    for (int p = 0; p < 4; p++)
#pragma unroll
                        for (int c = 0; c < 4; c++) {
                            float lo, hi;
                            unpack2(lo, hi, tmp[p][c]);
                            dst[(ebase + 2 * p) * 16 + kq + c] += lo;
                            dst[(ebase + 2 * p + 1) * 16 + kq + c] += hi;
                        }
                }
            } else {
#pragma unroll
                for (int mm = 0; mm < 3; mm++) {
                    ull cp[4];
#pragma unroll
                    for (int p = 0; p < 4; p++)
                        cp[p] = *(const ull*)&cDT[mm * 1056 + ig * 66 + ebase + 2 * p];
                    ull tmp[4][4];
#pragma unroll
                    for (int p = 0; p < 4; p++)
#pragma unroll
                        for (int c = 0; c < 4; c++) tmp[p][c] = fmul2(cp[p], acc[p][c]);
#pragma unroll
                    for (int m = 4; m <= 16; m <<= 1)
#pragma unroll
                        for (int p = 0; p < 4; p++)
#pragma unroll
                            for (int c = 0; c < 4; c++)
                                tmp[p][c] = fadd2(tmp[p][c], shflx64(tmp[p][c], m));
                    if (lane < 4) {
#pragma unroll
                        for (int p = 0; p < 4; p++)
#pragma unroll
                            for (int c = 0; c < 4; c++) {
                                float lo, hi;
                                unpack2(lo, hi, tmp[p][c]);
                                vout[(ebase + 2 * p) * 48 + (kq + c) * 3 + mm] += lo;
                                vout[(ebase + 2 * p + 1) * 48 + (kq + c) * 3 + mm] += hi;
                            }
                    }
                }
            }
        }
    }

    // --- scatter (each warp flushes its own 8 edges; owner-exclusive smem) ---
    if (lane < 4) {
#pragma unroll
        for (int q = 0; q < 8; q++) {
            int e = ebase + q;
            int src = srcs[e];
            float sv0 = shsm[e * 4 + 1], sv1 = shsm[e * 4 + 2], sv2 = shsm[e * 4 + 3];
#pragma unroll
            for (int c = 0; c < 4; c++) {
                int k = kq + c;
                atomicAdd(&g_agg[src * 64 + k], sout[e * 16 + k]);
                float r = rout[e * 16 + k];
                atomicAdd(&g_agg[src * 64 + 16 + k * 3 + 0], vout[e * 48 + k * 3 + 0] + sv0 * r);
                atomicAdd(&g_agg[src * 64 + 16 + k * 3 + 1], vout[e * 48 + k * 3 + 1] + sv1 * r);
                atomicAdd(&g_agg[src * 64 + 16 + k * 3 + 2], vout[e * 48 + k * 3 + 2] + sv2 * r);
            }
        }
    } else if (lane == 4) {
#pragma unroll
        for (int q = 0; q < 8; q++) atomicAdd(&g_cnt[srcs[ebase + q]], 1.0f);
    }
}

// ---------------- kernel 3: mean + residual + BN stats ----------------
__global__ __launch_bounds__(256) void k_stats(const float* __restrict__ node_attr) {
    __shared__ float sstat[48];
    int tid = threadIdx.x;
    if (tid < 48) sstat[tid] = 0.0f;
    __syncthreads();

    int n = blockIdx.x * 16 + (tid >> 4);
    int q = tid & 15;
    if (n < N_NODES) {
        float inv = 1.0f / fmaxf(g_cnt[n], 1.0f);
        float4 ag = *(const float4*)&g_agg[n * 64 + q * 4];
        float4 na = *(const float4*)&node_attr[n * 64 + q * 4];
        float o[4] = {fmaf(ag.x, inv, na.x), fmaf(ag.y, inv, na.y),
                      fmaf(ag.z, inv, na.z), fmaf(ag.w, inv, na.w)};
        *(float4*)&g_out[n * 64 + q * 4] = make_float4(o[0], o[1], o[2], o[3]);
        if (q < 4) {
#pragma unroll
            for (int t = 0; t < 4; t++) {
                atomicAdd(&sstat[q * 4 + t], o[t]);
                atomicAdd(&sstat[16 + q * 4 + t], o[t] * o[t]);
            }
        } else {
#pragma unroll
            for (int t = 0; t < 4; t++) {
                int k = (q * 4 + t - 16) / 3;
                atomicAdd(&sstat[32 + k], o[t] * o[t]);
            }
        }
    }
    __syncthreads();
    if (tid < 48) atomicAdd(&g_stats[tid], sstat[tid]);
}

// ---------------- kernel 4: finalize BN params ----------------
__global__ void k_finalize(const float* __restrict__ bn_weight) {
    int t = threadIdx.x;
    if (t < 16) {
        float mean = g_stats[t] * (1.0f / N_NODES);
        float var = g_stats[16 + t] * (1.0f / N_NODES) - mean * mean;
        g_norm[t] = mean;
        g_norm[16 + t] = bn_weight[t] * rsqrtf(var + BN_EPS);
        float fn = g_stats[32 + t] * (1.0f / (3.0f * N_NODES));
        g_norm[32 + t] = bn_weight[16 + t] * rsqrtf(fn + BN_EPS);
    }
}

// ---------------- kernel 5: normalize ----------------
__global__ void k_norm(const float* __restrict__ bn_bias, float* __restrict__ out) {
    int idx = blockIdx.x * blockDim.x + threadIdx.x;
    if (idx >= N_NODES * 64) return;
    int f = idx & 63;
    float o = g_out[idx];
    if (f < 16)
        out[idx] = (o - g_norm[f]) * g_norm[16 + f] + bn_bias[f];
    else
        out[idx] = o * g_norm[32 + (f - 16) / 3];
}

// ---------------- launch ----------------
extern "C" void kernel_launch(void* const* d_in, const int* in_sizes, int n_in,
                              void* d_out, int out_size) {
    const float* node_attr = (const float*)d_in[0];
    const float* edge_attr = (const float*)d_in[1];
    const float* edge_sh = (const float*)d_in[2];
    const float* w1 = (const float*)d_in[3];
    const float* b1 = (const float*)d_in[4];
    const float* w2 = (const float*)d_in[5];
    const float* b2 = (const float*)d_in[6];
    const float* bnw = (const float*)d_in[7];
    const float* bnb = (const float*)d_in[8];
    const int* eidx = (const int*)d_in[9];
    float* out = (float*)d_out;

    const int SMEM_G1 = (64 * HS + 64 * 64) * 4;
    const int SMEM_TP =
        (64 * 72 + 64 * 128 + 3 * 1056 + 3168 + 1024 + 1024 + 3072 + 1024 + 256) * 4;
    cudaFuncSetAttribute(k_gemm1, cudaFuncAttributeMaxDynamicSharedMemorySize, SMEM_G1);
    cudaFuncSetAttribute(k_tp, cudaFuncAttributeMaxDynamicSharedMemorySize, SMEM_TP);

    k_zero<<<512, 256>>>();
    k_gemm1<<<N_EDGES / 64, 256, SMEM_G1>>>(edge_attr, w1, b1);
    k_tp<<<N_EDGES / 64, 256, SMEM_TP>>>(node_attr, edge_sh, w2, b2, eidx);
    k_stats<<<(N_NODES + 15) / 16, 256>>>(node_attr);
    k_finalize<<<1, 32>>>(bnw);
    k_norm<<<(N_NODES * 64 + 255) / 256, 256>>>(bnb, out);
}

// round 5
// speedup vs baseline: 2.9746x; 1.9179x over previous
#include <cuda_runtime.h>
#include <cuda_bf16.h>

#define N_NODES 50000
#define N_EDGES 200000
#define MUL 16
#define ALPHA 0.17677669529663687f
#define INV_SQRT3 0.5773502691896258f
#define AIS (ALPHA * INV_SQRT3)
#define BN_EPS 1e-5f
#define HS 132

typedef unsigned long long ull;
typedef unsigned int u32;

// ---------------- fp32x2 helpers (k_gemm1) ----------------
__device__ __forceinline__ ull ffma2(ull a, ull b, ull c) {
    ull d;
    asm("fma.rn.f32x2 %0, %1, %2, %3;" : "=l"(d) : "l"(a), "l"(b), "l"(c));
    return d;
}
__device__ __forceinline__ void unpack2(float& lo, float& hi, ull v) {
    asm("mov.b64 {%0, %1}, %2;" : "=f"(lo), "=f"(hi) : "l"(v));
}

// ---------------- mma / ldmatrix helpers (baseline PTX, no 'a' features) ----------------
__device__ __forceinline__ u32 smem_u32(const void* p) {
    u32 a;
    asm("{ .reg .u64 t; cvta.to.shared.u64 t, %1; cvt.u32.u64 %0, t; }" : "=r"(a) : "l"(p));
    return a;
}
__device__ __forceinline__ void ldsm4(u32& r0, u32& r1, u32& r2, u32& r3, u32 addr) {
    asm volatile("ldmatrix.sync.aligned.m8n8.x4.shared.b16 {%0,%1,%2,%3}, [%4];"
                 : "=r"(r0), "=r"(r1), "=r"(r2), "=r"(r3) : "r"(addr));
}
__device__ __forceinline__ void mma16816(float* d, u32 a0, u32 a1, u32 a2, u32 a3,
                                         u32 b0, u32 b1) {
    asm volatile(
        "mma.sync.aligned.m16n8k16.row.col.f32.bf16.bf16.f32 "
        "{%0,%1,%2,%3}, {%4,%5,%6,%7}, {%8,%9}, {%0,%1,%2,%3};"
        : "+f"(d[0]), "+f"(d[1]), "+f"(d[2]), "+f"(d[3])
        : "r"(a0), "r"(a1), "r"(a2), "r"(a3), "r"(b0), "r"(b1));
}

// ---------------- scratch ----------------
__device__ __align__(16) __nv_bfloat16 g_Hhi[N_EDGES * 64];
__device__ __align__(16) __nv_bfloat16 g_Hlo[N_EDGES * 64];
__device__ __align__(16) __nv_bfloat16 g_BThi[1024 * 64];
__device__ __align__(16) __nv_bfloat16 g_BTlo[1024 * 64];
__device__ float g_agg[N_NODES * 64];
__device__ float g_cnt[N_NODES];
__device__ float g_out[N_NODES * 64];
__device__ float g_stats[48];
__device__ float g_norm[48];

// ---------------- kernel 0: zero ----------------
__global__ void k_zero() {
    int idx = blockIdx.x * blockDim.x + threadIdx.x;
    int stride = gridDim.x * blockDim.x;
    for (int i = idx; i < N_NODES * 64; i += stride) g_agg[i] = 0.0f;
    for (int i = idx; i < N_NODES; i += stride) g_cnt[i] = 0.0f;
    if (idx < 48) g_stats[idx] = 0.0f;
}

// ---------------- kernel 0b: split W2^T into bf16 hi/lo ----------------
__global__ void k_wsplit(const float* __restrict__ w2) {
    int idx = blockIdx.x * blockDim.x + threadIdx.x;
    if (idx >= 64 * 1024) return;
    int j = idx >> 10, c = idx & 1023;
    float v = w2[idx];
    __nv_bfloat16 hi = __float2bfloat16(v);
    float lo = v - __bfloat162float(hi);
    g_BThi[c * 64 + j] = hi;
    g_BTlo[c * 64 + j] = __float2bfloat16(lo);
}

// ---------------- kernel 1: H = relu(EA @ W1 + b1), bf16 hi/lo output ----------------
__global__ __launch_bounds__(256) void k_gemm1(const float* __restrict__ ea,
                                               const float* __restrict__ w1,
                                               const float* __restrict__ b1) {
    extern __shared__ __align__(16) float smg[];
    float* eaT2 = smg;
    float* w1s = eaT2 + 64 * HS;
    int tid = threadIdx.x;
    int e0 = blockIdx.x * 64;

    for (int idx = tid; idx < 4096; idx += 256) {
        int e = idx >> 6, j = idx & 63;
        float v = ea[(e0 + e) * 64 + j];
        eaT2[j * HS + 2 * e] = v;
        eaT2[j * HS + 2 * e + 1] = v;
        w1s[idx] = w1[idx];
    }
    __syncthreads();

    int te = (tid >> 4) << 2;
    int tc = (tid & 15) << 2;
    ull acc2[4][2];
#pragma unroll
    for (int a = 0; a < 4; a++) { acc2[a][0] = 0ULL; acc2[a][1] = 0ULL; }

#pragma unroll 4
    for (int j = 0; j < 64; j++) {
        ulonglong2 e01 = *(const ulonglong2*)&eaT2[j * HS + 2 * te];
        ulonglong2 e23 = *(const ulonglong2*)&eaT2[j * HS + 2 * te + 4];
        ulonglong2 wq = *(const ulonglong2*)&w1s[j * 64 + tc];
        ull hd[4] = {e01.x, e01.y, e23.x, e23.y};
        ull wp[2] = {wq.x, wq.y};
#pragma unroll
        for (int a = 0; a < 4; a++)
#pragma unroll
            for (int p = 0; p < 2; p++) acc2[a][p] = ffma2(hd[a], wp[p], acc2[a][p]);
    }

    float bb[4] = {b1[tc], b1[tc + 1], b1[tc + 2], b1[tc + 3]};
#pragma unroll
    for (int a = 0; a < 4; a++) {
        float o[4];
        unpack2(o[0], o[1], acc2[a][0]);
        unpack2(o[2], o[3], acc2[a][1]);
        __nv_bfloat162 hh[2], ll[2];
#pragma unroll
        for (int q = 0; q < 4; q++) {
            float v = fmaxf(o[q] + bb[q], 0.0f);
            __nv_bfloat16 hi = __float2bfloat16(v);
            float lo = v - __bfloat162float(hi);
            if (q & 1) { hh[q >> 1].y = hi; ll[q >> 1].y = __float2bfloat16(lo); }
            else       { hh[q >> 1].x = hi; ll[q >> 1].x = __float2bfloat16(lo); }
        }
        int base = (e0 + te + a) * 64 + tc;
        *(__nv_bfloat162*)&g_Hhi[base] = hh[0];
        *(__nv_bfloat162*)&g_Hhi[base + 2] = hh[1];
        *(__nv_bfloat162*)&g_Hlo[base] = ll[0];
        *(__nv_bfloat162*)&g_Hlo[base + 2] = ll[1];
    }
}

// ---------------- kernel 2: mma.sync GEMM2 + TP + scatter ----------------
// 256 threads, 128 edges/block. Warp w owns edge tile [w*16, w*16+16).
// 16 slices (t in 0..3 chunks x g in 0..3 col-groups of 64). Per slice:
// 3-pass bf16-split HMMA into D[16e x 64c] frags, then in-register contraction.
#define OFF_AHI 0
#define OFF_ALO 18432
#define OFF_BHI 36864
#define OFF_BLO 46080
#define OFF_CA 55296
#define OFF_CB 63744
#define OFF_CX 72192
#define OFF_CD 80640
#define OFF_B2 105984
#define OFF_SHS 110080
#define SMEM_TP 112128

__global__ __launch_bounds__(256, 2) void k_tp(const float* __restrict__ node_attr,
                                               const float* __restrict__ edge_sh,
                                               const float* __restrict__ b2,
                                               const int* __restrict__ edge_index) {
    extern __shared__ __align__(16) char smem[];
    float* cA = (float*)(smem + OFF_CA);
    float* cB = (float*)(smem + OFF_CB);
    float* cX = (float*)(smem + OFF_CX);
    float* cD = (float*)(smem + OFF_CD);
    float* b2s = (float*)(smem + OFF_B2);
    float* shs = (float*)(smem + OFF_SHS);
    __shared__ int srcs[128], dsts[128];

    int tid = threadIdx.x;
    int lane = tid & 31;
    int wid = tid >> 5;
    int e0 = blockIdx.x * 128;
    u32 sbase = smem_u32(smem);

    if (tid < 128) {
        int e = e0 + tid;
        bool val = e < N_EDGES;
        float4 sh = val ? ((const float4*)edge_sh)[e] : make_float4(0, 0, 0, 0);
        *(float4*)&shs[tid * 4] = sh;
        srcs[tid] = val ? edge_index[e] : 0;
        dsts[tid] = val ? edge_index[N_EDGES + e] : -1;
    }
    for (int idx = tid; idx < 1024; idx += 256) b2s[idx] = b2[idx];
    __syncthreads();

    // A tiles (bf16 hi/lo), rows padded to 144B
    for (int idx = tid; idx < 1024; idx += 256) {
        int rr = idx >> 3, qq = idx & 7;
        int ge = e0 + rr;
        uint4 vh = make_uint4(0, 0, 0, 0), vl = vh;
        if (ge < N_EDGES) {
            vh = ((const uint4*)g_Hhi)[ge * 8 + qq];
            vl = ((const uint4*)g_Hlo)[ge * 8 + qq];
        }
        *(uint4*)(smem + OFF_AHI + rr * 144 + qq * 16) = vh;
        *(uint4*)(smem + OFF_ALO + rr * 144 + qq * 16) = vl;
    }
    // coefficients [i][132e]
    for (int idx = tid; idx < 2048; idx += 256) {
        int e = idx >> 4, i = idx & 15;
        int d = dsts[e];
        float ss = shs[e * 4], s1 = shs[e * 4 + 1], s2 = shs[e * 4 + 2], s3 = shs[e * 4 + 3];
        float xs = 0, x0 = 0, x1 = 0, x2 = 0;
        if (d >= 0) {
            xs = node_attr[d * 64 + i];
            const float* xp = &node_attr[d * 64 + 16 + 3 * i];
            x0 = xp[0]; x1 = xp[1]; x2 = xp[2];
        }
        cA[i * 132 + e] = ALPHA * ss * xs;
        cX[i * 132 + e] = AIS * xs;
        cB[i * 132 + e] = AIS * (x0 * s1 + x1 * s2 + x2 * s3);
        cD[(0 * 16 + i) * 132 + e] = AIS * ss * x0;
        cD[(1 * 16 + i) * 132 + e] = AIS * ss * x1;
        cD[(2 * 16 + i) * 132 + e] = AIS * ss * x2;
    }

    // ldmatrix lane offsets (bytes)
    u32 laneA = (u32)((wid * 16 + (lane & 7) + ((lane >> 3) & 1) * 8) * 144 +
                      ((lane >> 4) & 1) * 16);
    u32 laneB = (u32)(((lane & 7) + ((lane >> 4) & 1) * 8) * 144 + ((lane >> 3) & 1) * 16);

    int q = lane & 3;
    int r = lane >> 2;
    int el0 = wid * 16 + r;

    float accS[2][4], accR[2][4], accV[2][4][3];
#pragma unroll
    for (int m = 0; m < 2; m++)
#pragma unroll
        for (int s = 0; s < 4; s++) {
            accS[m][s] = 0; accR[m][s] = 0;
            accV[m][s][0] = 0; accV[m][s][1] = 0; accV[m][s][2] = 0;
        }

    for (int sl = 0; sl < 16; sl++) {
        int t = sl >> 2, g = sl & 3;
        __syncthreads();
        // load B slice [64n x 64k] hi/lo
        for (int idx = tid; idx < 512; idx += 256) {
            int rr = idx >> 3, qq = idx & 7;
            int gn = t * 256 + g * 64 + rr;
            *(uint4*)(smem + OFF_BHI + rr * 144 + qq * 16) = ((const uint4*)g_BThi)[gn * 8 + qq];
            *(uint4*)(smem + OFF_BLO + rr * 144 + qq * 16) = ((const uint4*)g_BTlo)[gn * 8 + qq];
        }
        __syncthreads();

        float d[32];
#pragma unroll
        for (int z = 0; z < 32; z++) d[z] = 0.0f;

#pragma unroll
        for (int p = 0; p < 3; p++) {
            u32 Ab = sbase + (p == 2 ? OFF_ALO : OFF_AHI) + laneA;
            u32 Bb = sbase + (p == 1 ? OFF_BLO : OFF_BHI) + laneB;
#pragma unroll
            for (int ks = 0; ks < 4; ks++) {
                u32 a0, a1, a2, a3;
                ldsm4(a0, a1, a2, a3, Ab + ks * 32);
#pragma unroll
                for (int bq = 0; bq < 4; bq++) {
                    u32 b0, b1, b2r, b3;
                    ldsm4(b0, b1, b2r, b3, Bb + bq * 2304 + ks * 32);
                    mma16816(&d[(2 * bq) * 4], a0, a1, a2, a3, b0, b1);
                    mma16816(&d[(2 * bq + 1) * 4], a0, a1, a2, a3, b2r, b3);
                }
            }
        }

        // contraction in fragment layout
        if (t < 2) {
            const float* cp = (t == 0) ? cA : cB;
#pragma unroll
            for (int n = 0; n < 8; n++) {
                int col = t * 256 + g * 64 + n * 8 + 2 * q;
                float bb0 = b2s[col], bb1 = b2s[col + 1];
                int i = g * 4 + (n >> 1);
                int sidx = (n & 1) * 2;
                float cv0 = cp[i * 132 + el0];
                float cv1 = cp[i * 132 + el0 + 8];
                accS[0][sidx]     += cv0 * (d[n * 4 + 0] + bb0);
                accS[0][sidx + 1] += cv0 * (d[n * 4 + 1] + bb1);
                accS[1][sidx]     += cv1 * (d[n * 4 + 2] + bb0);
                accS[1][sidx + 1] += cv1 * (d[n * 4 + 3] + bb1);
            }
        } else if (t == 2) {
#pragma unroll
            for (int n = 0; n < 8; n++) {
                int col = 512 + g * 64 + n * 8 + 2 * q;
                float bb0 = b2s[col], bb1 = b2s[col + 1];
                int i = g * 4 + (n >> 1);
                int sidx = (n & 1) * 2;
                float cv0 = cX[i * 132 + el0];
                float cv1 = cX[i * 132 + el0 + 8];
                accR[0][sidx]     += cv0 * (d[n * 4 + 0] + bb0);
                accR[0][sidx + 1] += cv0 * (d[n * 4 + 1] + bb1);
                accR[1][sidx]     += cv1 * (d[n * 4 + 2] + bb0);
                accR[1][sidx + 1] += cv1 * (d[n * 4 + 3] + bb1);
            }
        } else {
#pragma unroll
            for (int n = 0; n < 8; n++) {
                int col = 768 + g * 64 + n * 8 + 2 * q;
                float bb0 = b2s[col], bb1 = b2s[col + 1];
                int i = g * 4 + (n >> 1);
                int sidx = (n & 1) * 2;
                float w00 = d[n * 4 + 0] + bb0, w01 = d[n * 4 + 1] + bb1;
                float w10 = d[n * 4 + 2] + bb0, w11 = d[n * 4 + 3] + bb1;
#pragma unroll
                for (int mm = 0; mm < 3; mm++) {
                    float cd0 = cD[(mm * 16 + i) * 132 + el0];
                    float cd1 = cD[(mm * 16 + i) * 132 + el0 + 8];
                    accV[0][sidx][mm]     += cd0 * w00;
                    accV[0][sidx + 1][mm] += cd0 * w01;
                    accV[1][sidx][mm]     += cd1 * w10;
                    accV[1][sidx + 1][mm] += cd1 * w11;
                }
            }
        }
    }

    // scatter
#pragma unroll
    for (int m = 0; m < 2; m++) {
        int el = el0 + 8 * m;
        if (e0 + el < N_EDGES) {
            int src = srcs[el];
            float s1 = shs[el * 4 + 1], s2 = shs[el * 4 + 2], s3 = shs[el * 4 + 3];
#pragma unroll
            for (int sidx = 0; sidx < 4; sidx++) {
                int k = ((sidx >> 1) << 3) + 2 * q + (sidx & 1);
                atomicAdd(&g_agg[src * 64 + k], accS[m][sidx]);
                float rv = accR[m][sidx];
                atomicAdd(&g_agg[src * 64 + 16 + k * 3 + 0], accV[m][sidx][0] + s1 * rv);
                atomicAdd(&g_agg[src * 64 + 16 + k * 3 + 1], accV[m][sidx][1] + s2 * rv);
                atomicAdd(&g_agg[src * 64 + 16 + k * 3 + 2], accV[m][sidx][2] + s3 * rv);
            }
            if (q == 0) atomicAdd(&g_cnt[src], 1.0f);
        }
    }
}

// ---------------- kernel 3: mean + residual + BN stats ----------------
__global__ __launch_bounds__(256) void k_stats(const float* __restrict__ node_attr) {
    __shared__ float sstat[48];
    int tid = threadIdx.x;
    if (tid < 48) sstat[tid] = 0.0f;
    __syncthreads();

    int n = blockIdx.x * 16 + (tid >> 4);
    int q = tid & 15;
    if (n < N_NODES) {
        float inv = 1.0f / fmaxf(g_cnt[n], 1.0f);
        float4 ag = *(const float4*)&g_agg[n * 64 + q * 4];
        float4 na = *(const float4*)&node_attr[n * 64 + q * 4];
        float o[4] = {fmaf(ag.x, inv, na.x), fmaf(ag.y, inv, na.y),
                      fmaf(ag.z, inv, na.z), fmaf(ag.w, inv, na.w)};
        *(float4*)&g_out[n * 64 + q * 4] = make_float4(o[0], o[1], o[2], o[3]);
        if (q < 4) {
#pragma unroll
            for (int t = 0; t < 4; t++) {
                atomicAdd(&sstat[q * 4 + t], o[t]);
                atomicAdd(&sstat[16 + q * 4 + t], o[t] * o[t]);
            }
        } else {
#pragma unroll
            for (int t = 0; t < 4; t++) {
                int k = (q * 4 + t - 16) / 3;
                atomicAdd(&sstat[32 + k], o[t] * o[t]);
            }
        }
    }
    __syncthreads();
    if (tid < 48) atomicAdd(&g_stats[tid], sstat[tid]);
}

// ---------------- kernel 4: finalize ----------------
__global__ void k_finalize(const float* __restrict__ bn_weight) {
    int t = threadIdx.x;
    if (t < 16) {
        float mean = g_stats[t] * (1.0f / N_NODES);
        float var = g_stats[16 + t] * (1.0f / N_NODES) - mean * mean;
        g_norm[t] = mean;
        g_norm[16 + t] = bn_weight[t] * rsqrtf(var + BN_EPS);
        float fn = g_stats[32 + t] * (1.0f / (3.0f * N_NODES));
        g_norm[32 + t] = bn_weight[16 + t] * rsqrtf(fn + BN_EPS);
    }
}

// ---------------- kernel 5: normalize ----------------
__global__ void k_norm(const float* __restrict__ bn_bias, float* __restrict__ out) {
    int idx = blockIdx.x * blockDim.x + threadIdx.x;
    if (idx >= N_NODES * 64) return;
    int f = idx & 63;
    float o = g_out[idx];
    if (f < 16)
        out[idx] = (o - g_norm[f]) * g_norm[16 + f] + bn_bias[f];
    else
        out[idx] = o * g_norm[32 + (f - 16) / 3];
}

// ---------------- launch ----------------
extern "C" void kernel_launch(void* const* d_in, const int* in_sizes, int n_in,
                              void* d_out, int out_size) {
    const float* node_attr = (const float*)d_in[0];
    const float* edge_attr = (const float*)d_in[1];
    const float* edge_sh = (const float*)d_in[2];
    const float* w1 = (const float*)d_in[3];
    const float* b1 = (const float*)d_in[4];
    const float* w2 = (const float*)d_in[5];
    const float* b2 = (const float*)d_in[6];
    const float* bnw = (const float*)d_in[7];
    const float* bnb = (const float*)d_in[8];
    const int* eidx = (const int*)d_in[9];
    float* out = (float*)d_out;

    const int SMEM_G1 = (64 * HS + 64 * 64) * 4;
    cudaFuncSetAttribute(k_gemm1, cudaFuncAttributeMaxDynamicSharedMemorySize, SMEM_G1);
    cudaFuncSetAttribute(k_tp, cudaFuncAttributeMaxDynamicSharedMemorySize, SMEM_TP);

    k_zero<<<512, 256>>>();
    k_wsplit<<<256, 256>>>(w2);
    k_gemm1<<<N_EDGES / 64, 256, SMEM_G1>>>(edge_attr, w1, b1);
    k_tp<<<(N_EDGES + 127) / 128, 256, SMEM_TP>>>(node_attr, edge_sh, b2, eidx);
    k_stats<<<(N_NODES + 15) / 16, 256>>>(node_attr);
    k_finalize<<<1, 32>>>(bnw);
    k_norm<<<(N_NODES * 64 + 255) / 256, 256>>>(bnb, out);
}

// round 6
// speedup vs baseline: 3.3978x; 1.1423x over previous
#include <cuda_runtime.h>
#include <cuda_bf16.h>

#define N_NODES 50000
#define N_EDGES 200000
#define MUL 16
#define ALPHA 0.17677669529663687f
#define INV_SQRT3 0.5773502691896258f
#define AIS (ALPHA * INV_SQRT3)
#define BN_EPS 1e-5f
#define HS 132

typedef unsigned long long ull;
typedef unsigned int u32;

// ---------------- fp32x2 helpers (k_gemm1) ----------------
__device__ __forceinline__ ull ffma2(ull a, ull b, ull c) {
    ull d;
    asm("fma.rn.f32x2 %0, %1, %2, %3;" : "=l"(d) : "l"(a), "l"(b), "l"(c));
    return d;
}
__device__ __forceinline__ void unpack2(float& lo, float& hi, ull v) {
    asm("mov.b64 {%0, %1}, %2;" : "=f"(lo), "=f"(hi) : "l"(v));
}

// ---------------- mma / ldmatrix / cp.async (baseline PTX, no 'a' gates) ----------------
__device__ __forceinline__ u32 smem_u32(const void* p) {
    u32 a;
    asm("{ .reg .u64 t; cvta.to.shared.u64 t, %1; cvt.u32.u64 %0, t; }" : "=r"(a) : "l"(p));
    return a;
}
__device__ __forceinline__ void ldsm4(u32& r0, u32& r1, u32& r2, u32& r3, u32 addr) {
    asm volatile("ldmatrix.sync.aligned.m8n8.x4.shared.b16 {%0,%1,%2,%3}, [%4];"
                 : "=r"(r0), "=r"(r1), "=r"(r2), "=r"(r3) : "r"(addr));
}
__device__ __forceinline__ void mma16816(float* d, u32 a0, u32 a1, u32 a2, u32 a3,
                                         u32 b0, u32 b1) {
    asm volatile(
        "mma.sync.aligned.m16n8k16.row.col.f32.bf16.bf16.f32 "
        "{%0,%1,%2,%3}, {%4,%5,%6,%7}, {%8,%9}, {%0,%1,%2,%3};"
        : "+f"(d[0]), "+f"(d[1]), "+f"(d[2]), "+f"(d[3])
        : "r"(a0), "r"(a1), "r"(a2), "r"(a3), "r"(b0), "r"(b1));
}
__device__ __forceinline__ void cpasync16(u32 dst, const void* src) {
    asm volatile("cp.async.ca.shared.global [%0], [%1], 16;" :: "r"(dst), "l"(src) : "memory");
}
#define CP_COMMIT() asm volatile("cp.async.commit_group;" ::: "memory")
#define CP_WAIT0() asm volatile("cp.async.wait_group 0;" ::: "memory")

// ---------------- scratch ----------------
__device__ __align__(16) __nv_bfloat16 g_Hhi[N_EDGES * 64];
__device__ __align__(16) __nv_bfloat16 g_Hlo[N_EDGES * 64];
__device__ __align__(16) __nv_bfloat16 g_BThi[1024 * 64];
__device__ __align__(16) __nv_bfloat16 g_BTlo[1024 * 64];
__device__ float g_agg[N_NODES * 64];
__device__ float g_cnt[N_NODES];
__device__ float g_out[N_NODES * 64];
__device__ float g_stats[48];
__device__ float g_norm[48];

// ---------------- kernel 0: zero ----------------
__global__ void k_zero() {
    int idx = blockIdx.x * blockDim.x + threadIdx.x;
    int stride = gridDim.x * blockDim.x;
    for (int i = idx; i < N_NODES * 64; i += stride) g_agg[i] = 0.0f;
    for (int i = idx; i < N_NODES; i += stride) g_cnt[i] = 0.0f;
    if (idx < 48) g_stats[idx] = 0.0f;
}

// ---------------- kernel 0b: split W2^T into bf16 hi/lo ----------------
__global__ void k_wsplit(const float* __restrict__ w2) {
    int idx = blockIdx.x * blockDim.x + threadIdx.x;
    if (idx >= 64 * 1024) return;
    int j = idx >> 10, c = idx & 1023;
    float v = w2[idx];
    __nv_bfloat16 hi = __float2bfloat16(v);
    float lo = v - __bfloat162float(hi);
    g_BThi[c * 64 + j] = hi;
    g_BTlo[c * 64 + j] = __float2bfloat16(lo);
}

// ---------------- kernel 1: H = relu(EA @ W1 + b1), bf16 hi/lo output ----------------
__global__ __launch_bounds__(256) void k_gemm1(const float* __restrict__ ea,
                                               const float* __restrict__ w1,
                                               const float* __restrict__ b1) {
    extern __shared__ __align__(16) float smg[];
    float* eaT2 = smg;
    float* w1s = eaT2 + 64 * HS;
    int tid = threadIdx.x;
    int e0 = blockIdx.x * 64;

    for (int idx = tid; idx < 4096; idx += 256) {
        int e = idx >> 6, j = idx & 63;
        float v = ea[(e0 + e) * 64 + j];
        eaT2[j * HS + 2 * e] = v;
        eaT2[j * HS + 2 * e + 1] = v;
        w1s[idx] = w1[idx];
    }
    __syncthreads();

    int te = (tid >> 4) << 2;
    int tc = (tid & 15) << 2;
    ull acc2[4][2];
#pragma unroll
    for (int a = 0; a < 4; a++) { acc2[a][0] = 0ULL; acc2[a][1] = 0ULL; }

#pragma unroll 4
    for (int j = 0; j < 64; j++) {
        ulonglong2 e01 = *(const ulonglong2*)&eaT2[j * HS + 2 * te];
        ulonglong2 e23 = *(const ulonglong2*)&eaT2[j * HS + 2 * te + 4];
        ulonglong2 wq = *(const ulonglong2*)&w1s[j * 64 + tc];
        ull hd[4] = {e01.x, e01.y, e23.x, e23.y};
        ull wp[2] = {wq.x, wq.y};
#pragma unroll
        for (int a = 0; a < 4; a++)
#pragma unroll
            for (int p = 0; p < 2; p++) acc2[a][p] = ffma2(hd[a], wp[p], acc2[a][p]);
    }

    float bb[4] = {b1[tc], b1[tc + 1], b1[tc + 2], b1[tc + 3]};
#pragma unroll
    for (int a = 0; a < 4; a++) {
        float o[4];
        unpack2(o[0], o[1], acc2[a][0]);
        unpack2(o[2], o[3], acc2[a][1]);
        __nv_bfloat162 hh[2], ll[2];
#pragma unroll
        for (int q = 0; q < 4; q++) {
            float v = fmaxf(o[q] + bb[q], 0.0f);
            __nv_bfloat16 hi = __float2bfloat16(v);
            float lo = v - __bfloat162float(hi);
            if (q & 1) { hh[q >> 1].y = hi; ll[q >> 1].y = __float2bfloat16(lo); }
            else       { hh[q >> 1].x = hi; ll[q >> 1].x = __float2bfloat16(lo); }
        }
        int base = (e0 + te + a) * 64 + tc;
        *(__nv_bfloat162*)&g_Hhi[base] = hh[0];
        *(__nv_bfloat162*)&g_Hhi[base + 2] = hh[1];
        *(__nv_bfloat162*)&g_Hlo[base] = ll[0];
        *(__nv_bfloat162*)&g_Hlo[base + 2] = ll[1];
    }
}

// ---------------- kernel 2: mma.sync GEMM2 + TP + scatter ----------------
// 256 threads, 128 edges/block. Persistent A frags in registers; B slices
// cp.async double-buffered into the (dead after prologue) A staging region.
// 16 slices x 4 bq-groups of 16 cols; D = 8 regs, contraction per bq.
#define OFF_AB 0            // 36864: prologue A hi/lo; mainloop B dbl buf (2 x 18432)
#define OFF_CA 36864
#define OFF_CB 45312
#define OFF_CX 53760
#define OFF_CD 62208
#define OFF_B2 87552
#define OFF_SHS 91648
#define SMEM_TP 93696

__global__ __launch_bounds__(256, 2) void k_tp(const float* __restrict__ node_attr,
                                               const float* __restrict__ edge_sh,
                                               const float* __restrict__ b2,
                                               const int* __restrict__ edge_index) {
    extern __shared__ __align__(16) char smem[];
    float* cA = (float*)(smem + OFF_CA);
    float* cB = (float*)(smem + OFF_CB);
    float* cX = (float*)(smem + OFF_CX);
    float* cD = (float*)(smem + OFF_CD);
    float* b2s = (float*)(smem + OFF_B2);
    float* shs = (float*)(smem + OFF_SHS);
    __shared__ int srcs[128], dsts[128];

    int tid = threadIdx.x;
    int lane = tid & 31;
    int wid = tid >> 5;
    int e0 = blockIdx.x * 128;
    u32 sbase = smem_u32(smem);

    if (tid < 128) {
        int e = e0 + tid;
        bool val = e < N_EDGES;
        float4 sh = val ? ((const float4*)edge_sh)[e] : make_float4(0, 0, 0, 0);
        *(float4*)&shs[tid * 4] = sh;
        srcs[tid] = val ? edge_index[e] : 0;
        dsts[tid] = val ? edge_index[N_EDGES + e] : -1;
    }
    for (int idx = tid; idx < 1024; idx += 256) b2s[idx] = b2[idx];
    __syncthreads();

    // A tiles (bf16 hi/lo) into overlay region, rows padded to 144B
    for (int idx = tid; idx < 1024; idx += 256) {
        int rr = idx >> 3, qq = idx & 7;
        int ge = e0 + rr;
        uint4 vh = make_uint4(0, 0, 0, 0), vl = vh;
        if (ge < N_EDGES) {
            vh = ((const uint4*)g_Hhi)[ge * 8 + qq];
            vl = ((const uint4*)g_Hlo)[ge * 8 + qq];
        }
        *(uint4*)(smem + OFF_AB + rr * 144 + qq * 16) = vh;
        *(uint4*)(smem + OFF_AB + 18432 + rr * 144 + qq * 16) = vl;
    }
    // coefficients [i][132e]
    for (int idx = tid; idx < 2048; idx += 256) {
        int e = idx >> 4, i = idx & 15;
        int d = dsts[e];
        float ss = shs[e * 4], s1 = shs[e * 4 + 1], s2 = shs[e * 4 + 2], s3 = shs[e * 4 + 3];
        float xs = 0, x0 = 0, x1 = 0, x2 = 0;
        if (d >= 0) {
            xs = node_attr[d * 64 + i];
            const float* xp = &node_attr[d * 64 + 16 + 3 * i];
            x0 = xp[0]; x1 = xp[1]; x2 = xp[2];
        }
        cA[i * 132 + e] = ALPHA * ss * xs;
        cX[i * 132 + e] = AIS * xs;
        cB[i * 132 + e] = AIS * (x0 * s1 + x1 * s2 + x2 * s3);
        cD[(0 * 16 + i) * 132 + e] = AIS * ss * x0;
        cD[(1 * 16 + i) * 132 + e] = AIS * ss * x1;
        cD[(2 * 16 + i) * 132 + e] = AIS * ss * x2;
    }
    __syncthreads();

    // persistent A fragments (hi/lo, 4 k-steps)
    u32 laneA = (u32)((wid * 16 + (lane & 7) + ((lane >> 3) & 1) * 8) * 144 +
                      ((lane >> 4) & 1) * 16);
    u32 aH[4][4], aL[4][4];
#pragma unroll
    for (int ks = 0; ks < 4; ks++) {
        ldsm4(aH[ks][0], aH[ks][1], aH[ks][2], aH[ks][3], sbase + OFF_AB + laneA + ks * 32);
        ldsm4(aL[ks][0], aL[ks][1], aL[ks][2], aL[ks][3],
              sbase + OFF_AB + 18432 + laneA + ks * 32);
    }
    __syncthreads();  // all warps done reading A before cp.async overwrites

    // issue B slice 0 into buffer 0
#pragma unroll 1
    for (int idx = tid; idx < 1024; idx += 256) {
        int half = idx >> 9, rem = idx & 511;
        int rr = rem >> 3, qq = rem & 7;
        const __nv_bfloat16* srcb = half ? g_BTlo : g_BThi;
        cpasync16(sbase + OFF_AB + half * 9216 + rr * 144 + qq * 16,
                  (const char*)srcb + rr * 128 + qq * 16);
    }
    CP_COMMIT();

    u32 laneB = (u32)(((lane & 7) + ((lane >> 4) & 1) * 8) * 144 + ((lane >> 3) & 1) * 16);
    int q = lane & 3;
    int r = lane >> 2;
    int el0 = wid * 16 + r;

    float accS[2][4], accR[2][4], accV[2][4][3];
#pragma unroll
    for (int m = 0; m < 2; m++)
#pragma unroll
        for (int s = 0; s < 4; s++) {
            accS[m][s] = 0; accR[m][s] = 0;
            accV[m][s][0] = 0; accV[m][s][1] = 0; accV[m][s][2] = 0;
        }

#pragma unroll 1
    for (int sl = 0; sl < 16; sl++) {
        int t = sl >> 2, g = sl & 3;
        int buf = sl & 1;
        CP_WAIT0();
        __syncthreads();  // slice sl ready in all lanes; compute(sl-1) fully done
        if (sl < 15) {
            int nb = (sl + 1) & 1;
            const char* bhp = (const char*)&g_BThi[(sl + 1) * 64 * 64];
            const char* blp = (const char*)&g_BTlo[(sl + 1) * 64 * 64];
#pragma unroll 1
            for (int idx = tid; idx < 1024; idx += 256) {
                int half = idx >> 9, rem = idx & 511;
                int rr = rem >> 3, qq = rem & 7;
                cpasync16(sbase + OFF_AB + nb * 18432 + half * 9216 + rr * 144 + qq * 16,
                          (half ? blp : bhp) + rr * 128 + qq * 16);
            }
            CP_COMMIT();
        }

        u32 bHbase = sbase + OFF_AB + buf * 18432 + laneB;
        u32 bLbase = bHbase + 9216;

#pragma unroll
        for (int bq = 0; bq < 4; bq++) {
            float d[8];
#pragma unroll
            for (int z = 0; z < 8; z++) d[z] = 0.0f;

#pragma unroll
            for (int ks = 0; ks < 4; ks++) {
                u32 bh0, bh1, bh2, bh3, bl0, bl1, bl2, bl3;
                ldsm4(bh0, bh1, bh2, bh3, bHbase + bq * 2304 + ks * 32);
                ldsm4(bl0, bl1, bl2, bl3, bLbase + bq * 2304 + ks * 32);
                mma16816(&d[0], aH[ks][0], aH[ks][1], aH[ks][2], aH[ks][3], bh0, bh1);
                mma16816(&d[4], aH[ks][0], aH[ks][1], aH[ks][2], aH[ks][3], bh2, bh3);
                mma16816(&d[0], aH[ks][0], aH[ks][1], aH[ks][2], aH[ks][3], bl0, bl1);
                mma16816(&d[4], aH[ks][0], aH[ks][1], aH[ks][2], aH[ks][3], bl2, bl3);
                mma16816(&d[0], aL[ks][0], aL[ks][1], aL[ks][2], aL[ks][3], bh0, bh1);
                mma16816(&d[4], aL[ks][0], aL[ks][1], aL[ks][2], aL[ks][3], bh2, bh3);
            }

            // contraction: i = 4g + bq is lane-invariant for this group
            int i = g * 4 + bq;
            int colb = g * 64 + bq * 16 + 2 * q;
            if (t < 3) {
                const float* cp = (t == 0) ? cA : (t == 1) ? cB : cX;
                float cv0 = cp[i * 132 + el0];
                float cv1 = cp[i * 132 + el0 + 8];
                float (*acc)[4] = (t == 2) ? accR : accS;
#pragma unroll
                for (int f = 0; f < 2; f++) {
                    float bb0 = b2s[t * 256 + colb + f * 8];
                    float bb1 = b2s[t * 256 + colb + f * 8 + 1];
                    acc[0][f * 2 + 0] += cv0 * (d[f * 4 + 0] + bb0);
                    acc[0][f * 2 + 1] += cv0 * (d[f * 4 + 1] + bb1);
                    acc[1][f * 2 + 0] += cv1 * (d[f * 4 + 2] + bb0);
                    acc[1][f * 2 + 1] += cv1 * (d[f * 4 + 3] + bb1);
                }
            } else {
                float cd0[3], cd1[3];
#pragma unroll
                for (int mm = 0; mm < 3; mm++) {
                    cd0[mm] = cD[(mm * 16 + i) * 132 + el0];
                    cd1[mm] = cD[(mm * 16 + i) * 132 + el0 + 8];
                }
#pragma unroll
                for (int f = 0; f < 2; f++) {
                    float bb0 = b2s[768 + colb + f * 8];
                    float bb1 = b2s[768 + colb + f * 8 + 1];
                    float w00 = d[f * 4 + 0] + bb0, w01 = d[f * 4 + 1] + bb1;
                    float w10 = d[f * 4 + 2] + bb0, w11 = d[f * 4 + 3] + bb1;
#pragma unroll
                    for (int mm = 0; mm < 3; mm++) {
                        accV[0][f * 2 + 0][mm] += cd0[mm] * w00;
                        accV[0][f * 2 + 1][mm] += cd0[mm] * w01;
                        accV[1][f * 2 + 0][mm] += cd1[mm] * w10;
                        accV[1][f * 2 + 1][mm] += cd1[mm] * w11;
                    }
                }
            }
        }
    }

    // scatter
#pragma unroll
    for (int m = 0; m < 2; m++) {
        int el = el0 + 8 * m;
        if (e0 + el < N_EDGES) {
            int src = srcs[el];
            float s1 = shs[el * 4 + 1], s2 = shs[el * 4 + 2], s3 = shs[el * 4 + 3];
#pragma unroll
            for (int sidx = 0; sidx < 4; sidx++) {
                int k = ((sidx >> 1) << 3) + 2 * q + (sidx & 1);
                atomicAdd(&g_agg[src * 64 + k], accS[m][sidx]);
                float rv = accR[m][sidx];
                atomicAdd(&g_agg[src * 64 + 16 + k * 3 + 0], accV[m][sidx][0] + s1 * rv);
                atomicAdd(&g_agg[src * 64 + 16 + k * 3 + 1], accV[m][sidx][1] + s2 * rv);
                atomicAdd(&g_agg[src * 64 + 16 + k * 3 + 2], accV[m][sidx][2] + s3 * rv);
            }
            if (q == 0) atomicAdd(&g_cnt[src], 1.0f);
        }
    }
}

// ---------------- kernel 3: mean + residual + BN stats ----------------
__global__ __launch_bounds__(256) void k_stats(const float* __restrict__ node_attr) {
    __shared__ float sstat[48];
    int tid = threadIdx.x;
    if (tid < 48) sstat[tid] = 0.0f;
    __syncthreads();

    int n = blockIdx.x * 16 + (tid >> 4);
    int q = tid & 15;
    if (n < N_NODES) {
        float inv = 1.0f / fmaxf(g_cnt[n], 1.0f);
        float4 ag = *(const float4*)&g_agg[n * 64 + q * 4];
        float4 na = *(const float4*)&node_attr[n * 64 + q * 4];
        float o[4] = {fmaf(ag.x, inv, na.x), fmaf(ag.y, inv, na.y),
                      fmaf(ag.z, inv, na.z), fmaf(ag.w, inv, na.w)};
        *(float4*)&g_out[n * 64 + q * 4] = make_float4(o[0], o[1], o[2], o[3]);
        if (q < 4) {
#pragma unroll
            for (int t = 0; t < 4; t++) {
                atomicAdd(&sstat[q * 4 + t], o[t]);
                atomicAdd(&sstat[16 + q * 4 + t], o[t] * o[t]);
            }
        } else {
#pragma unroll
            for (int t = 0; t < 4; t++) {
                int k = (q * 4 + t - 16) / 3;
                atomicAdd(&sstat[32 + k], o[t] * o[t]);
            }
        }
    }
    __syncthreads();
    if (tid < 48) atomicAdd(&g_stats[tid], sstat[tid]);
}

// ---------------- kernel 4: finalize ----------------
__global__ void k_finalize(const float* __restrict__ bn_weight) {
    int t = threadIdx.x;
    if (t < 16) {
        float mean = g_stats[t] * (1.0f / N_NODES);
        float var = g_stats[16 + t] * (1.0f / N_NODES) - mean * mean;
        g_norm[t] = mean;
        g_norm[16 + t] = bn_weight[t] * rsqrtf(var + BN_EPS);
        float fn = g_stats[32 + t] * (1.0f / (3.0f * N_NODES));
        g_norm[32 + t] = bn_weight[16 + t] * rsqrtf(fn + BN_EPS);
    }
}

// ---------------- kernel 5: normalize ----------------
__global__ void k_norm(const float* __restrict__ bn_bias, float* __restrict__ out) {
    int idx = blockIdx.x * blockDim.x + threadIdx.x;
    if (idx >= N_NODES * 64) return;
    int f = idx & 63;
    float o = g_out[idx];
    if (f < 16)
        out[idx] = (o - g_norm[f]) * g_norm[16 + f] + bn_bias[f];
    else
        out[idx] = o * g_norm[32 + (f - 16) / 3];
}

// ---------------- launch ----------------
extern "C" void kernel_launch(void* const* d_in, const int* in_sizes, int n_in,
                              void* d_out, int out_size) {
    const float* node_attr = (const float*)d_in[0];
    const float* edge_attr = (const float*)d_in[1];
    const float* edge_sh = (const float*)d_in[2];
    const float* w1 = (const float*)d_in[3];
    const float* b1 = (const float*)d_in[4];
    const float* w2 = (const float*)d_in[5];
    const float* b2 = (const float*)d_in[6];
    const float* bnw = (const float*)d_in[7];
    const float* bnb = (const float*)d_in[8];
    const int* eidx = (const int*)d_in[9];
    float* out = (float*)d_out;

    const int SMEM_G1 = (64 * HS + 64 * 64) * 4;
    cudaFuncSetAttribute(k_gemm1, cudaFuncAttributeMaxDynamicSharedMemorySize, SMEM_G1);
    cudaFuncSetAttribute(k_tp, cudaFuncAttributeMaxDynamicSharedMemorySize, SMEM_TP);

    k_zero<<<512, 256>>>();
    k_wsplit<<<256, 256>>>(w2);
    k_gemm1<<<N_EDGES / 64, 256, SMEM_G1>>>(edge_attr, w1, b1);
    k_tp<<<(N_EDGES + 127) / 128, 256, SMEM_TP>>>(node_attr, edge_sh, b2, eidx);
    k_stats<<<(N_NODES + 15) / 16, 256>>>(node_attr);
    k_finalize<<<1, 32>>>(bnw);
    k_norm<<<(N_NODES * 64 + 255) / 256, 256>>>(bnb, out);
}